// round 12
// baseline (speedup 1.0000x reference)
#include <cuda_runtime.h>
#include <cuda_fp16.h>
#include <cstdint>
#include <cstddef>

// Problem dims (fixed by the dataset)
#define M_DIM   8192      // 4*2048 rows of x
#define IN_DIM  4096      // K of main GEMM
#define OUT_DIM 11008     // N of main GEMM
#define RANK_   192
#define KPACK   576       // 3 * RANK_  (compensated-product K concat)

// ---------------------------------------------------------------------------
// Scratch (static __device__ arrays — allocation-free per harness rules)
// ---------------------------------------------------------------------------
__device__ __align__(256) float  g_w  [(size_t)OUT_DIM * IN_DIM];  // weight+delta fp32
__device__ __align__(256) __half g_xh [(size_t)M_DIM  * IN_DIM];   // x as fp16
__device__ __align__(256) __half g_wh [(size_t)OUT_DIM * IN_DIM];  // quantized w fp16
__device__ __align__(256) __half g_bdp[(size_t)OUT_DIM * KPACK];   // [Ah|Ah|Al] of 64*Bd
__device__ __align__(256) __half g_bup[(size_t)IN_DIM * KPACK];    // [Bh|Bl|Bh] of 64*Bu, [N,K]

// ---------------------------------------------------------------------------
// x -> fp16
// ---------------------------------------------------------------------------
__global__ void cvt_half_kernel(const float* __restrict__ in,
                                __half* __restrict__ out, int n4) {
    int i = blockIdx.x * 256 + threadIdx.x;
    if (i < n4) {
        float4 v = reinterpret_cast<const float4*>(in)[i];
        __half2 h0 = __floats2half2_rn(v.x, v.y);
        __half2 h1 = __floats2half2_rn(v.z, v.w);
        uint2 p;
        p.x = *reinterpret_cast<uint32_t*>(&h0);
        p.y = *reinterpret_cast<uint32_t*>(&h1);
        reinterpret_cast<uint2*>(out)[i] = p;
    }
}

// ---------------------------------------------------------------------------
// Pack kernels: hi/lo fp16 split of 64*Bd / 64*Bu, K-concatenated so that a
// single fp16 GEMM computes Ah*Bh + Ah*Bl + Al*Bh (fp32-accurate product).
// ---------------------------------------------------------------------------
__global__ void pack_bd_kernel(const float* __restrict__ bd,
                               __half* __restrict__ out) {
    size_t i = (size_t)blockIdx.x * 256 + threadIdx.x;
    if (i < (size_t)OUT_DIM * KPACK) {
        int o = (int)(i / KPACK), c = (int)(i % KPACK);
        int r = (c < 192) ? c : ((c < 384) ? c - 192 : c - 384);
        float v = bd[(size_t)o * RANK_ + r] * 64.0f;
        __half h = __float2half_rn(v);
        out[i] = (c < 384) ? h : __float2half_rn(v - __half2float(h));
    }
}

__global__ void pack_bu_kernel(const float* __restrict__ bu,
                               __half* __restrict__ out) {
    size_t i = (size_t)blockIdx.x * 256 + threadIdx.x;
    if (i < (size_t)IN_DIM * KPACK) {
        int n = (int)(i / KPACK), c = (int)(i % KPACK);
        int r = (c < 192) ? c : ((c < 384) ? c - 192 : c - 384);
        float v = bu[(size_t)r * IN_DIM + n] * 64.0f;
        __half h = __float2half_rn(v);
        out[i] = (c < 192 || c >= 384) ? h
                                       : __float2half_rn(v - __half2float(h));
    }
}

// ---------------------------------------------------------------------------
// Row-wise 4-bit asymmetric fake quant: fp32 g_w (row cached) -> fp16 g_wh.
// ---------------------------------------------------------------------------
__global__ void quant_kernel(const float* __restrict__ w, __half* __restrict__ wh) {
    __shared__ float row[IN_DIM];
    __shared__ float smn[8], smx[8];
    __shared__ float s_scale, s_zero;

    const int rix = blockIdx.x;
    const float* p = w + (size_t)rix * IN_DIM;
    __half* po = wh + (size_t)rix * IN_DIM;
    const int tid = threadIdx.x;

    float mn = 0.0f, mx = 0.0f;
    #pragma unroll
    for (int i = tid; i < IN_DIM / 4; i += 256) {
        float4 v = reinterpret_cast<const float4*>(p)[i];
        reinterpret_cast<float4*>(row)[i] = v;
        mn = fminf(mn, fminf(fminf(v.x, v.y), fminf(v.z, v.w)));
        mx = fmaxf(mx, fmaxf(fmaxf(v.x, v.y), fmaxf(v.z, v.w)));
    }
    #pragma unroll
    for (int o = 16; o; o >>= 1) {
        mn = fminf(mn, __shfl_xor_sync(0xffffffffu, mn, o));
        mx = fmaxf(mx, __shfl_xor_sync(0xffffffffu, mx, o));
    }
    const int warp = tid >> 5, lane = tid & 31;
    if (lane == 0) { smn[warp] = mn; smx[warp] = mx; }
    __syncthreads();
    if (tid == 0) {
        float a = smn[0], b = smx[0];
        #pragma unroll
        for (int i = 1; i < 8; i++) { a = fminf(a, smn[i]); b = fmaxf(b, smx[i]); }
        float sc = fmaxf((b - a) / 15.0f, 1e-8f);
        s_scale = sc;
        s_zero  = rintf(-a / sc);
    }
    __syncthreads();
    const float sc = s_scale, z = s_zero;

    #pragma unroll
    for (int i = tid; i < IN_DIM / 4; i += 256) {
        float4 v = reinterpret_cast<float4*>(row)[i];
        float q0 = (fminf(fmaxf(rintf(v.x / sc) + z, 0.0f), 15.0f) - z) * sc;
        float q1 = (fminf(fmaxf(rintf(v.y / sc) + z, 0.0f), 15.0f) - z) * sc;
        float q2 = (fminf(fmaxf(rintf(v.z / sc) + z, 0.0f), 15.0f) - z) * sc;
        float q3 = (fminf(fmaxf(rintf(v.w / sc) + z, 0.0f), 15.0f) - z) * sc;
        __half2 h0 = __floats2half2_rn(q0, q1);
        __half2 h1 = __floats2half2_rn(q2, q3);
        uint2 pk;
        pk.x = *reinterpret_cast<uint32_t*>(&h0);
        pk.y = *reinterpret_cast<uint32_t*>(&h1);
        reinterpret_cast<uint2*>(po)[i] = pk;
    }
}

// ---------------------------------------------------------------------------
// Shared GEMM building blocks
// ---------------------------------------------------------------------------
__device__ __forceinline__ void cp16(uint32_t s, const void* g) {
    asm volatile("cp.async.cg.shared.global [%0], [%1], 16;\n" :: "r"(s), "l"(g));
}
__device__ __forceinline__ void ldsm_x4(uint32_t* r, uint32_t addr) {
    asm volatile("ldmatrix.sync.aligned.m8n8.x4.shared.b16 {%0,%1,%2,%3}, [%4];"
                 : "=r"(r[0]), "=r"(r[1]), "=r"(r[2]), "=r"(r[3]) : "r"(addr));
}
__device__ __forceinline__ void mma_f16(float* d, const uint32_t* a,
                                        uint32_t b0, uint32_t b1) {
    asm volatile(
        "mma.sync.aligned.m16n8k16.row.col.f32.f16.f16.f32 "
        "{%0,%1,%2,%3}, {%4,%5,%6,%7}, {%8,%9}, {%0,%1,%2,%3};\n"
        : "+f"(d[0]), "+f"(d[1]), "+f"(d[2]), "+f"(d[3])
        : "r"(a[0]), "r"(a[1]), "r"(a[2]), "r"(a[3]), "r"(b0), "r"(b1));
}

#define BKH 64
#define ROWB 144
#define NSTAGE 3
#define KTILES_MAIN (IN_DIM / BKH)        // 64
#define KTILES_DELTA (KPACK / BKH)        // 9

// Main GEMM tile geometry: 128x128, 128 threads (4 warps, 2Mx2N, warp 64x64)
#define BM 128
#define BN 128
#define A_BYTES (BM * ROWB)               // 18432
#define B_BYTES (BN * ROWB)               // 18432
#define STAGE_BYTES (A_BYTES + B_BYTES)   // 36864
#define GEMM_SMEM (NSTAGE * STAGE_BYTES)  // 110592
#define MTILES (M_DIM / BM)               // 64
#define NTILES (OUT_DIM / BN)             // 86

// Delta GEMM tile geometry: 256x128, 512 threads (16 warps, 4Mx4N, warp 64x32)
#define DBM 256
#define DBN 128
#define DA_BYTES (DBM * ROWB)             // 36864
#define DB_BYTES (DBN * ROWB)             // 18432
#define DSTAGE_BYTES (DA_BYTES + DB_BYTES) // 55296
#define DGEMM_SMEM (NSTAGE * DSTAGE_BYTES) // 165888
#define EPI_STRIDE 136                    // floats; conflict-free staging

// ---------------------------------------------------------------------------
// Delta GEMM (fp16, K=576): g_w[11008, 4096] = weight + (bdp @ bup^T)/4096
// 256x128 CTA tile, 512 threads, 1 CTA/SM.
// ---------------------------------------------------------------------------
__global__ __launch_bounds__(512, 1)
void gemm_delta_f16(const __half* __restrict__ ap, const __half* __restrict__ bp,
                    const float* __restrict__ wgt, float* __restrict__ outw) {
    extern __shared__ __align__(128) unsigned char smem[];
    const uint32_t sb = (uint32_t)__cvta_generic_to_shared(smem);
    const int tid = threadIdx.x, warp = tid >> 5, lane = tid & 31;
    const int wm = warp & 3, wn = warp >> 2;   // 4M x 4N, warp tile 64x32

    const int mBase = blockIdx.y * DBM, nBase = blockIdx.x * DBN;

    // cp.async: A = 256 rows x 8 chunks = 2048 → 4/thread; B = 1024 → 2/thread
    const int r0 = tid >> 3, s0 = tid & 7;
    const __half* gA0 = ap + (size_t)(mBase + r0) * KPACK + s0 * 8;
    const __half* gB0 = bp + (size_t)(nBase + r0) * KPACK + s0 * 8;
    const uint32_t sA0 = r0 * ROWB + s0 * 16;
    const uint32_t sB0 = DA_BYTES + r0 * ROWB + s0 * 16;

    auto issue = [&](int kt) {
        const uint32_t base = sb + (uint32_t)(kt % NSTAGE) * DSTAGE_BYTES;
        const int koff = kt * BKH;
        #pragma unroll
        for (int i = 0; i < 4; i++)
            cp16(base + sA0 + i * (64 * ROWB), gA0 + koff + (size_t)i * 64 * KPACK);
        #pragma unroll
        for (int i = 0; i < 2; i++)
            cp16(base + sB0 + i * (64 * ROWB), gB0 + koff + (size_t)i * 64 * KPACK);
        asm volatile("cp.async.commit_group;\n");
    };

    const int mat = lane >> 3, mrow = lane & 7;
    const uint32_t aAddr0 = (uint32_t)(wm * 64 + ((mat & 1) << 3) + mrow) * ROWB
                          + ((mat >> 1) << 4);
    const uint32_t bAddr0 = DA_BYTES
                          + (uint32_t)(wn * 32 + ((mat >> 1) << 3) + mrow) * ROWB
                          + ((mat & 1) << 4);

    float acc[4][4][4];
    #pragma unroll
    for (int i = 0; i < 4; i++)
        #pragma unroll
        for (int j = 0; j < 4; j++)
            #pragma unroll
            for (int k = 0; k < 4; k++) acc[i][j][k] = 0.0f;

    issue(0); issue(1);

    for (int kt = 0; kt < KTILES_DELTA; ++kt) {
        if (kt < KTILES_DELTA - 1) { asm volatile("cp.async.wait_group 1;\n"); }
        else                       { asm volatile("cp.async.wait_group 0;\n"); }
        __syncthreads();
        if (kt + 2 < KTILES_DELTA) issue(kt + 2);

        const uint32_t base = sb + (uint32_t)(kt % NSTAGE) * DSTAGE_BYTES;

        #pragma unroll
        for (int kk = 0; kk < 4; ++kk) {
            uint32_t af[4][4], bf[2][4];
            #pragma unroll
            for (int mi = 0; mi < 4; ++mi)
                ldsm_x4(af[mi], base + aAddr0 + mi * (16 * ROWB) + kk * 32);
            #pragma unroll
            for (int nj = 0; nj < 2; ++nj)
                ldsm_x4(bf[nj], base + bAddr0 + nj * (16 * ROWB) + kk * 32);
            #pragma unroll
            for (int mi = 0; mi < 4; ++mi) {
                #pragma unroll
                for (int nj = 0; nj < 2; ++nj) {
                    mma_f16(acc[mi][nj * 2],     af[mi], bf[nj][0], bf[nj][1]);
                    mma_f16(acc[mi][nj * 2 + 1], af[mi], bf[nj][2], bf[nj][3]);
                }
            }
        }
    }

    // Epilogue via smem staging (256x128 tile, conflict-free), then stream
    // coalesced float4: out = acc/4096 + weight.
    __syncthreads();
    float* st = reinterpret_cast<float*>(smem);
    {
        const int mr = wm * 64 + (lane >> 2);
        const int nc = wn * 32 + ((lane & 3) << 1);
        #pragma unroll
        for (int mi = 0; mi < 4; ++mi) {
            const int m0 = mr + mi * 16;
            #pragma unroll
            for (int njh = 0; njh < 4; ++njh) {
                const int n = nc + njh * 8;
                st[m0 * EPI_STRIDE + n]           = acc[mi][njh][0];
                st[m0 * EPI_STRIDE + n + 1]       = acc[mi][njh][1];
                st[(m0 + 8) * EPI_STRIDE + n]     = acc[mi][njh][2];
                st[(m0 + 8) * EPI_STRIDE + n + 1] = acc[mi][njh][3];
            }
        }
    }
    __syncthreads();
    const float SC = 1.0f / 4096.0f;
    #pragma unroll
    for (int it = 0; it < 16; ++it) {
        int i = tid + it * 512;                  // 0..8191 float4 slots
        int row = i >> 5, c4 = i & 31;
        float4 v = *reinterpret_cast<float4*>(&st[row * EPI_STRIDE + c4 * 4]);
        size_t gofs = (size_t)(mBase + row) * IN_DIM + nBase + c4 * 4;
        float4 w4 = *reinterpret_cast<const float4*>(&wgt[gofs]);
        v.x = v.x * SC + w4.x;
        v.y = v.y * SC + w4.y;
        v.z = v.z * SC + w4.z;
        v.w = v.w * SC + w4.w;
        *reinterpret_cast<float4*>(&outw[gofs]) = v;
    }
}

// ---------------------------------------------------------------------------
// Main GEMM: out[8192,11008] = xh @ wh^T + bias
// R12: 128 threads, 4 warps (2Mx2N), warp tile 64x64 — halves redundant
// ldmatrix traffic per MMA (smem-BW ceiling was binding).
// ---------------------------------------------------------------------------
__global__ __launch_bounds__(128, 2)
void gemm_main_fp16(const __half* __restrict__ xh, const __half* __restrict__ wh,
                    const float* __restrict__ bias, float* __restrict__ out) {
    extern __shared__ __align__(128) unsigned char smem[];
    const uint32_t sb = (uint32_t)__cvta_generic_to_shared(smem);
    const int tid = threadIdx.x, warp = tid >> 5, lane = tid & 31;
    const int wm = warp & 1, wn = warp >> 1;   // 2M x 2N warps, warp tile 64x64

    // Grid swizzle: 8-wide n-supercolumns (86 = 10*8 + 6).
    int g = blockIdx.x, mTile, nTile;
    if (g < MTILES * 80) { int sc = g >> 9, loc = g & 511; nTile = sc * 8 + (loc & 7); mTile = loc >> 3; }
    else                 { int loc = g - MTILES * 80; nTile = 80 + loc % 6; mTile = loc / 6; }
    const int mBase = mTile * BM, nBase = nTile * BN;

    // cp.async: A = 128 rows x 8 chunks = 1024 → 8/thread (stride 16 rows); B same
    const int r0 = tid >> 3, s0 = tid & 7;
    const __half* gA0 = xh + (size_t)(mBase + r0) * IN_DIM + s0 * 8;
    const __half* gB0 = wh + (size_t)(nBase + r0) * IN_DIM + s0 * 8;
    const uint32_t sA0 = r0 * ROWB + s0 * 16;
    const uint32_t sB0 = A_BYTES + r0 * ROWB + s0 * 16;

    auto issue = [&](int kt) {
        const uint32_t base = sb + (uint32_t)(kt % NSTAGE) * STAGE_BYTES;
        const int koff = kt * BKH;
        #pragma unroll
        for (int i = 0; i < 8; i++)
            cp16(base + sA0 + i * (16 * ROWB), gA0 + koff + (size_t)i * 16 * IN_DIM);
        #pragma unroll
        for (int i = 0; i < 8; i++)
            cp16(base + sB0 + i * (16 * ROWB), gB0 + koff + (size_t)i * 16 * IN_DIM);
        asm volatile("cp.async.commit_group;\n");
    };

    const int mat = lane >> 3, mrow = lane & 7;
    const uint32_t aAddr0 = (uint32_t)(wm * 64 + ((mat & 1) << 3) + mrow) * ROWB
                          + ((mat >> 1) << 4);
    const uint32_t bAddr0 = A_BYTES
                          + (uint32_t)(wn * 64 + ((mat >> 1) << 3) + mrow) * ROWB
                          + ((mat & 1) << 4);

    float acc[4][8][4];
    #pragma unroll
    for (int i = 0; i < 4; i++)
        #pragma unroll
        for (int j = 0; j < 8; j++)
            #pragma unroll
            for (int k = 0; k < 4; k++) acc[i][j][k] = 0.0f;

    issue(0); issue(1);

    for (int kt = 0; kt < KTILES_MAIN; ++kt) {
        if (kt < KTILES_MAIN - 1) { asm volatile("cp.async.wait_group 1;\n"); }
        else                      { asm volatile("cp.async.wait_group 0;\n"); }
        __syncthreads();
        if (kt + 2 < KTILES_MAIN) issue(kt + 2);

        const uint32_t base = sb + (uint32_t)(kt % NSTAGE) * STAGE_BYTES;

        #pragma unroll
        for (int kk = 0; kk < 4; ++kk) {
            uint32_t af[4][4], bf[4][4];
            #pragma unroll
            for (int mi = 0; mi < 4; ++mi)
                ldsm_x4(af[mi], base + aAddr0 + mi * (16 * ROWB) + kk * 32);
            #pragma unroll
            for (int nj = 0; nj < 4; ++nj)
                ldsm_x4(bf[nj], base + bAddr0 + nj * (16 * ROWB) + kk * 32);
            #pragma unroll
            for (int mi = 0; mi < 4; ++mi) {
                #pragma unroll
                for (int nj = 0; nj < 4; ++nj) {
                    mma_f16(acc[mi][nj * 2],     af[mi], bf[nj][0], bf[nj][1]);
                    mma_f16(acc[mi][nj * 2 + 1], af[mi], bf[nj][2], bf[nj][3]);
                }
            }
        }
    }

    // Epilogue: warp tile 64x64 at (wm*64, wn*64)
    const int mRow = mBase + wm * 64 + (lane >> 2);
    const int nCol = nBase + wn * 64 + ((lane & 3) << 1);
    #pragma unroll
    for (int mi = 0; mi < 4; ++mi) {
        const int m0 = mRow + mi * 16;
        #pragma unroll
        for (int njh = 0; njh < 8; ++njh) {
            const int n = nCol + njh * 8;
            float2 b2 = *reinterpret_cast<const float2*>(&bias[n]);
            float2 o0 = make_float2(acc[mi][njh][0] + b2.x, acc[mi][njh][1] + b2.y);
            float2 o1 = make_float2(acc[mi][njh][2] + b2.x, acc[mi][njh][3] + b2.y);
            *reinterpret_cast<float2*>(&out[(size_t)m0 * OUT_DIM + n])       = o0;
            *reinterpret_cast<float2*>(&out[(size_t)(m0 + 8) * OUT_DIM + n]) = o1;
        }
    }
}

// ---------------------------------------------------------------------------
// Launch
// ---------------------------------------------------------------------------
extern "C" void kernel_launch(void* const* d_in, const int* in_sizes, int n_in,
                              void* d_out, int out_size) {
    const float *x = nullptr, *weight = nullptr, *Bd = nullptr,
                *Bu = nullptr, *bias = nullptr;
    for (int i = 0; i < n_in; i++) {
        switch (in_sizes[i]) {
            case 33554432: x      = (const float*)d_in[i]; break;  // 8192*4096
            case 45088768: weight = (const float*)d_in[i]; break;  // 11008*4096
            case 2113536:  Bd     = (const float*)d_in[i]; break;  // 11008*192
            case 786432:   Bu     = (const float*)d_in[i]; break;  // 192*4096
            case 11008:    bias   = (const float*)d_in[i]; break;
        }
    }
    if (!x && n_in > 0)      x      = (const float*)d_in[0];
    if (!weight && n_in > 1) weight = (const float*)d_in[1];
    if (!Bd && n_in > 2)     Bd     = (const float*)d_in[2];
    if (!Bu && n_in > 3)     Bu     = (const float*)d_in[3];
    if (!bias && n_in > 4)   bias   = (const float*)d_in[4];

    float *gw;
    __half *gxh, *gwh, *gbdp, *gbup;
    cudaGetSymbolAddress((void**)&gw,   g_w);
    cudaGetSymbolAddress((void**)&gxh,  g_xh);
    cudaGetSymbolAddress((void**)&gwh,  g_wh);
    cudaGetSymbolAddress((void**)&gbdp, g_bdp);
    cudaGetSymbolAddress((void**)&gbup, g_bup);

    cudaFuncSetAttribute(gemm_delta_f16,
                         cudaFuncAttributeMaxDynamicSharedMemorySize, DGEMM_SMEM);
    cudaFuncSetAttribute(gemm_main_fp16,
                         cudaFuncAttributeMaxDynamicSharedMemorySize, GEMM_SMEM);

    // 1) x -> fp16;  Bd/Bu -> packed hi/lo fp16 (K=576 concat, x64 scaled)
    cvt_half_kernel<<<(33554432 / 4 + 255) / 256, 256>>>(x, gxh, 33554432 / 4);
    pack_bd_kernel<<<((size_t)OUT_DIM * KPACK + 255) / 256, 256>>>(Bd, gbdp);
    pack_bu_kernel<<<((size_t)IN_DIM * KPACK + 255) / 256, 256>>>(Bu, gbup);

    // 2) g_w = weight + Bd@Bu via single fp16 GEMM (K=576, 256x128 tiles)
    gemm_delta_f16<<<dim3(IN_DIM / DBN, OUT_DIM / DBM), 512, DGEMM_SMEM>>>(
        gbdp, gbup, weight, gw);

    // 3) fake-quant rows of g_w (fp32 decisions, single pass), emit fp16 g_wh
    quant_kernel<<<OUT_DIM, 256>>>(gw, gwh);

    // 4) out = xh @ wh^T + bias (128x128 tiles, 2 CTA/SM, warp tile 64x64)
    gemm_main_fp16<<<MTILES * NTILES, 128, GEMM_SMEM>>>(gxh, gwh, bias,
                                                        (float*)d_out);
}

// round 13
// speedup vs baseline: 1.0417x; 1.0417x over previous
#include <cuda_runtime.h>
#include <cuda_fp16.h>
#include <cstdint>
#include <cstddef>

// Problem dims (fixed by the dataset)
#define M_DIM   8192      // 4*2048 rows of x
#define IN_DIM  4096      // K of main GEMM
#define OUT_DIM 11008     // N of main GEMM
#define RANK_   192
#define KPACK   576       // 3 * RANK_  (compensated-product K concat)

// ---------------------------------------------------------------------------
// Scratch (static __device__ arrays — allocation-free per harness rules)
// ---------------------------------------------------------------------------
__device__ __align__(256) float  g_w  [(size_t)OUT_DIM * IN_DIM];  // weight+delta fp32
__device__ __align__(256) __half g_xh [(size_t)M_DIM  * IN_DIM];   // x as fp16
__device__ __align__(256) __half g_wh [(size_t)OUT_DIM * IN_DIM];  // quantized w fp16
__device__ __align__(256) __half g_bdp[(size_t)OUT_DIM * KPACK];   // [Ah|Ah|Al] of 64*Bd
__device__ __align__(256) __half g_bup[(size_t)IN_DIM * KPACK];    // [Bh|Bl|Bh] of 64*Bu, [N,K]

// ---------------------------------------------------------------------------
// x -> fp16
// ---------------------------------------------------------------------------
__global__ void cvt_half_kernel(const float* __restrict__ in,
                                __half* __restrict__ out, int n4) {
    int i = blockIdx.x * 256 + threadIdx.x;
    if (i < n4) {
        float4 v = reinterpret_cast<const float4*>(in)[i];
        __half2 h0 = __floats2half2_rn(v.x, v.y);
        __half2 h1 = __floats2half2_rn(v.z, v.w);
        uint2 p;
        p.x = *reinterpret_cast<uint32_t*>(&h0);
        p.y = *reinterpret_cast<uint32_t*>(&h1);
        reinterpret_cast<uint2*>(out)[i] = p;
    }
}

// ---------------------------------------------------------------------------
// Pack kernels: hi/lo fp16 split of 64*Bd / 64*Bu, K-concatenated so that a
// single fp16 GEMM computes Ah*Bh + Ah*Bl + Al*Bh (fp32-accurate product).
// ---------------------------------------------------------------------------
__global__ void pack_bd_kernel(const float* __restrict__ bd,
                               __half* __restrict__ out) {
    size_t i = (size_t)blockIdx.x * 256 + threadIdx.x;
    if (i < (size_t)OUT_DIM * KPACK) {
        int o = (int)(i / KPACK), c = (int)(i % KPACK);
        int r = (c < 192) ? c : ((c < 384) ? c - 192 : c - 384);
        float v = bd[(size_t)o * RANK_ + r] * 64.0f;
        __half h = __float2half_rn(v);
        out[i] = (c < 384) ? h : __float2half_rn(v - __half2float(h));
    }
}

// R13: tiled-transpose pack for Bu — coalesced reads AND writes.
// in:  bu[r][n], r in [0,192), n in [0,4096)
// out: out[n][c]: c<192 hi(bu[c][n]); 192..383 lo(bu[c-192][n]); >=384 hi again
__global__ void pack_bu_kernel(const float* __restrict__ bu,
                               __half* __restrict__ out) {
    __shared__ float t[32][33];
    const int r0 = blockIdx.x * 32;       // 6 blocks over rank
    const int n0 = blockIdx.y * 32;       // 128 blocks over IN_DIM
    const int tx = threadIdx.x, ty = threadIdx.y;   // 32 x 8

    #pragma unroll
    for (int j = 0; j < 32; j += 8)
        t[ty + j][tx] = bu[(size_t)(r0 + ty + j) * IN_DIM + n0 + tx];
    __syncthreads();

    #pragma unroll
    for (int j = 0; j < 32; j += 8) {
        const int n = n0 + ty + j;
        float v = t[tx][ty + j] * 64.0f;
        __half h = __float2half_rn(v);
        __half l = __float2half_rn(v - __half2float(h));
        __half* o = out + (size_t)n * KPACK + r0 + tx;
        o[0]   = h;
        o[192] = l;
        o[384] = h;
    }
}

// ---------------------------------------------------------------------------
// Row-wise 4-bit asymmetric fake quant: fp32 g_w (row cached) -> fp16 g_wh.
// ---------------------------------------------------------------------------
__global__ void quant_kernel(const float* __restrict__ w, __half* __restrict__ wh) {
    __shared__ float row[IN_DIM];
    __shared__ float smn[8], smx[8];
    __shared__ float s_scale, s_zero;

    const int rix = blockIdx.x;
    const float* p = w + (size_t)rix * IN_DIM;
    __half* po = wh + (size_t)rix * IN_DIM;
    const int tid = threadIdx.x;

    float mn = 0.0f, mx = 0.0f;
    #pragma unroll
    for (int i = tid; i < IN_DIM / 4; i += 256) {
        float4 v = reinterpret_cast<const float4*>(p)[i];
        reinterpret_cast<float4*>(row)[i] = v;
        mn = fminf(mn, fminf(fminf(v.x, v.y), fminf(v.z, v.w)));
        mx = fmaxf(mx, fmaxf(fmaxf(v.x, v.y), fmaxf(v.z, v.w)));
    }
    #pragma unroll
    for (int o = 16; o; o >>= 1) {
        mn = fminf(mn, __shfl_xor_sync(0xffffffffu, mn, o));
        mx = fmaxf(mx, __shfl_xor_sync(0xffffffffu, mx, o));
    }
    const int warp = tid >> 5, lane = tid & 31;
    if (lane == 0) { smn[warp] = mn; smx[warp] = mx; }
    __syncthreads();
    if (tid == 0) {
        float a = smn[0], b = smx[0];
        #pragma unroll
        for (int i = 1; i < 8; i++) { a = fminf(a, smn[i]); b = fmaxf(b, smx[i]); }
        float sc = fmaxf((b - a) / 15.0f, 1e-8f);
        s_scale = sc;
        s_zero  = rintf(-a / sc);
    }
    __syncthreads();
    const float sc = s_scale, z = s_zero;

    #pragma unroll
    for (int i = tid; i < IN_DIM / 4; i += 256) {
        float4 v = reinterpret_cast<float4*>(row)[i];
        float q0 = (fminf(fmaxf(rintf(v.x / sc) + z, 0.0f), 15.0f) - z) * sc;
        float q1 = (fminf(fmaxf(rintf(v.y / sc) + z, 0.0f), 15.0f) - z) * sc;
        float q2 = (fminf(fmaxf(rintf(v.z / sc) + z, 0.0f), 15.0f) - z) * sc;
        float q3 = (fminf(fmaxf(rintf(v.w / sc) + z, 0.0f), 15.0f) - z) * sc;
        __half2 h0 = __floats2half2_rn(q0, q1);
        __half2 h1 = __floats2half2_rn(q2, q3);
        uint2 pk;
        pk.x = *reinterpret_cast<uint32_t*>(&h0);
        pk.y = *reinterpret_cast<uint32_t*>(&h1);
        reinterpret_cast<uint2*>(po)[i] = pk;
    }
}

// ---------------------------------------------------------------------------
// Shared GEMM building blocks
// ---------------------------------------------------------------------------
__device__ __forceinline__ void cp16(uint32_t s, const void* g) {
    asm volatile("cp.async.cg.shared.global [%0], [%1], 16;\n" :: "r"(s), "l"(g));
}
__device__ __forceinline__ void ldsm_x4(uint32_t* r, uint32_t addr) {
    asm volatile("ldmatrix.sync.aligned.m8n8.x4.shared.b16 {%0,%1,%2,%3}, [%4];"
                 : "=r"(r[0]), "=r"(r[1]), "=r"(r[2]), "=r"(r[3]) : "r"(addr));
}
__device__ __forceinline__ void mma_f16(float* d, const uint32_t* a,
                                        uint32_t b0, uint32_t b1) {
    asm volatile(
        "mma.sync.aligned.m16n8k16.row.col.f32.f16.f16.f32 "
        "{%0,%1,%2,%3}, {%4,%5,%6,%7}, {%8,%9}, {%0,%1,%2,%3};\n"
        : "+f"(d[0]), "+f"(d[1]), "+f"(d[2]), "+f"(d[3])
        : "r"(a[0]), "r"(a[1]), "r"(a[2]), "r"(a[3]), "r"(b0), "r"(b1));
}

// Common tile geometry (both GEMMs): CTA 128x128, 256 thr, 2 CTA/SM,
// K-chunk 64 halves, ROWB=144, 3-stage cp.async.  (Proven optimum: R9/R11.)
#define BM 128
#define BN 128
#define BKH 64
#define ROWB 144
#define A_BYTES (BM * ROWB)               // 18432
#define B_BYTES (BN * ROWB)               // 18432
#define STAGE_BYTES (A_BYTES + B_BYTES)   // 36864
#define NSTAGE 3
#define GEMM_SMEM (NSTAGE * STAGE_BYTES)  // 110592
#define KTILES_MAIN (IN_DIM / BKH)        // 64
#define KTILES_DELTA (KPACK / BKH)        // 9
#define MTILES (M_DIM / BM)               // 64
#define NTILES (OUT_DIM / BN)             // 86
#define EPI_STRIDE 136                    // floats; conflict-free staging

// ---------------------------------------------------------------------------
// Delta GEMM (fp16, K=576): g_w[11008, 4096] = weight + (bdp @ bup^T)/4096
// (R11 config: 128x128, 256 thr, 2 CTA/SM, smem-staged coalesced epilogue)
// ---------------------------------------------------------------------------
__global__ __launch_bounds__(256, 2)
void gemm_delta_f16(const __half* __restrict__ ap, const __half* __restrict__ bp,
                    const float* __restrict__ wgt, float* __restrict__ outw) {
    extern __shared__ __align__(128) unsigned char smem[];
    const uint32_t sb = (uint32_t)__cvta_generic_to_shared(smem);
    const int tid = threadIdx.x, warp = tid >> 5, lane = tid & 31;
    const int wm = warp & 1, wn = warp >> 1;   // 2M x 4N, warp tile 64x32

    const int mBase = blockIdx.y * BM, nBase = blockIdx.x * BN;

    const __half* gA[4]; uint32_t sAoff[4];
    const __half* gB[4]; uint32_t sBoff[4];
    #pragma unroll
    for (int i = 0; i < 4; i++) {
        int c = tid + i * 256;
        int r = c >> 3, s = c & 7;
        gA[i] = ap + (size_t)(mBase + r) * KPACK + s * 8;
        sAoff[i] = r * ROWB + s * 16;
        gB[i] = bp + (size_t)(nBase + r) * KPACK + s * 8;
        sBoff[i] = A_BYTES + r * ROWB + s * 16;
    }

    auto issue = [&](int kt) {
        const uint32_t base = sb + (uint32_t)(kt % NSTAGE) * STAGE_BYTES;
        const int koff = kt * BKH;
        #pragma unroll
        for (int i = 0; i < 4; i++) cp16(base + sAoff[i], gA[i] + koff);
        #pragma unroll
        for (int i = 0; i < 4; i++) cp16(base + sBoff[i], gB[i] + koff);
        asm volatile("cp.async.commit_group;\n");
    };

    const int mat = lane >> 3, mrow = lane & 7;
    const uint32_t aAddr0 = (uint32_t)(wm * 64 + ((mat & 1) << 3) + mrow) * ROWB
                          + ((mat >> 1) << 4);
    const uint32_t bAddr0 = A_BYTES
                          + (uint32_t)(wn * 32 + ((mat >> 1) << 3) + mrow) * ROWB
                          + ((mat & 1) << 4);

    float acc[4][4][4];
    #pragma unroll
    for (int i = 0; i < 4; i++)
        #pragma unroll
        for (int j = 0; j < 4; j++)
            #pragma unroll
            for (int k = 0; k < 4; k++) acc[i][j][k] = 0.0f;

    issue(0); issue(1);

    for (int kt = 0; kt < KTILES_DELTA; ++kt) {
        if (kt < KTILES_DELTA - 1) { asm volatile("cp.async.wait_group 1;\n"); }
        else                       { asm volatile("cp.async.wait_group 0;\n"); }
        __syncthreads();
        if (kt + 2 < KTILES_DELTA) issue(kt + 2);

        const uint32_t base = sb + (uint32_t)(kt % NSTAGE) * STAGE_BYTES;

        #pragma unroll
        for (int kk = 0; kk < 4; ++kk) {
            uint32_t af[4][4], bf[2][4];
            #pragma unroll
            for (int mi = 0; mi < 4; ++mi)
                ldsm_x4(af[mi], base + aAddr0 + mi * (16 * ROWB) + kk * 32);
            #pragma unroll
            for (int nj = 0; nj < 2; ++nj)
                ldsm_x4(bf[nj], base + bAddr0 + nj * (16 * ROWB) + kk * 32);
            #pragma unroll
            for (int mi = 0; mi < 4; ++mi) {
                #pragma unroll
                for (int nj = 0; nj < 2; ++nj) {
                    mma_f16(acc[mi][nj * 2],     af[mi], bf[nj][0], bf[nj][1]);
                    mma_f16(acc[mi][nj * 2 + 1], af[mi], bf[nj][2], bf[nj][3]);
                }
            }
        }
    }

    // Epilogue via smem staging (conflict-free), then coalesced float4 stream.
    __syncthreads();
    float* st = reinterpret_cast<float*>(smem);
    {
        const int mr = wm * 64 + (lane >> 2);
        const int nc = wn * 32 + ((lane & 3) << 1);
        #pragma unroll
        for (int mi = 0; mi < 4; ++mi) {
            const int m0 = mr + mi * 16;
            #pragma unroll
            for (int njh = 0; njh < 4; ++njh) {
                const int n = nc + njh * 8;
                st[m0 * EPI_STRIDE + n]           = acc[mi][njh][0];
                st[m0 * EPI_STRIDE + n + 1]       = acc[mi][njh][1];
                st[(m0 + 8) * EPI_STRIDE + n]     = acc[mi][njh][2];
                st[(m0 + 8) * EPI_STRIDE + n + 1] = acc[mi][njh][3];
            }
        }
    }
    __syncthreads();
    const float SC = 1.0f / 4096.0f;
    #pragma unroll
    for (int it = 0; it < 16; ++it) {
        int i = tid + it * 256;                  // 0..4095 float4 slots
        int row = i >> 5, c4 = i & 31;
        float4 v = *reinterpret_cast<float4*>(&st[row * EPI_STRIDE + c4 * 4]);
        size_t gofs = (size_t)(mBase + row) * IN_DIM + nBase + c4 * 4;
        float4 w4 = *reinterpret_cast<const float4*>(&wgt[gofs]);
        v.x = v.x * SC + w4.x;
        v.y = v.y * SC + w4.y;
        v.z = v.z * SC + w4.z;
        v.w = v.w * SC + w4.w;
        *reinterpret_cast<float4*>(&outw[gofs]) = v;
    }
}

// ---------------------------------------------------------------------------
// Main GEMM: out[8192,11008] = xh @ wh^T + bias
// (R9/R11 config: 128x128, 256 thr, 2 CTA/SM, BKH=64, 3-stage, 64 barriers)
// ---------------------------------------------------------------------------
__global__ __launch_bounds__(256, 2)
void gemm_main_fp16(const __half* __restrict__ xh, const __half* __restrict__ wh,
                    const float* __restrict__ bias, float* __restrict__ out) {
    extern __shared__ __align__(128) unsigned char smem[];
    const uint32_t sb = (uint32_t)__cvta_generic_to_shared(smem);
    const int tid = threadIdx.x, warp = tid >> 5, lane = tid & 31;
    const int wm = warp & 1, wn = warp >> 1;   // 2M x 4N warps, warp tile 64x32

    // Grid swizzle: 8-wide n-supercolumns (86 = 10*8 + 6).
    int g = blockIdx.x, mTile, nTile;
    if (g < MTILES * 80) { int sc = g >> 9, loc = g & 511; nTile = sc * 8 + (loc & 7); mTile = loc >> 3; }
    else                 { int loc = g - MTILES * 80; nTile = 80 + loc % 6; mTile = loc / 6; }
    const int mBase = mTile * BM, nBase = nTile * BN;

    const __half* gA[4]; uint32_t sAoff[4];
    const __half* gB[4]; uint32_t sBoff[4];
    #pragma unroll
    for (int i = 0; i < 4; i++) {
        int c = tid + i * 256;
        int r = c >> 3, s = c & 7;
        gA[i] = xh + (size_t)(mBase + r) * IN_DIM + s * 8;
        sAoff[i] = r * ROWB + s * 16;
        gB[i] = wh + (size_t)(nBase + r) * IN_DIM + s * 8;
        sBoff[i] = A_BYTES + r * ROWB + s * 16;
    }

    auto issue = [&](int kt) {
        const uint32_t base = sb + (uint32_t)(kt % NSTAGE) * STAGE_BYTES;
        const int koff = kt * BKH;
        #pragma unroll
        for (int i = 0; i < 4; i++) cp16(base + sAoff[i], gA[i] + koff);
        #pragma unroll
        for (int i = 0; i < 4; i++) cp16(base + sBoff[i], gB[i] + koff);
        asm volatile("cp.async.commit_group;\n");
    };

    const int mat = lane >> 3, mrow = lane & 7;
    const uint32_t aAddr0 = (uint32_t)(wm * 64 + ((mat & 1) << 3) + mrow) * ROWB
                          + ((mat >> 1) << 4);
    const uint32_t bAddr0 = A_BYTES
                          + (uint32_t)(wn * 32 + ((mat >> 1) << 3) + mrow) * ROWB
                          + ((mat & 1) << 4);

    float acc[4][4][4];
    #pragma unroll
    for (int i = 0; i < 4; i++)
        #pragma unroll
        for (int j = 0; j < 4; j++)
            #pragma unroll
            for (int k = 0; k < 4; k++) acc[i][j][k] = 0.0f;

    issue(0); issue(1);

    for (int kt = 0; kt < KTILES_MAIN; ++kt) {
        if (kt < KTILES_MAIN - 1) { asm volatile("cp.async.wait_group 1;\n"); }
        else                      { asm volatile("cp.async.wait_group 0;\n"); }
        __syncthreads();
        if (kt + 2 < KTILES_MAIN) issue(kt + 2);

        const uint32_t base = sb + (uint32_t)(kt % NSTAGE) * STAGE_BYTES;

        #pragma unroll
        for (int kk = 0; kk < 4; ++kk) {
            uint32_t af[4][4], bf[2][4];
            #pragma unroll
            for (int mi = 0; mi < 4; ++mi)
                ldsm_x4(af[mi], base + aAddr0 + mi * (16 * ROWB) + kk * 32);
            #pragma unroll
            for (int nj = 0; nj < 2; ++nj)
                ldsm_x4(bf[nj], base + bAddr0 + nj * (16 * ROWB) + kk * 32);
            #pragma unroll
            for (int mi = 0; mi < 4; ++mi) {
                #pragma unroll
                for (int nj = 0; nj < 2; ++nj) {
                    mma_f16(acc[mi][nj * 2],     af[mi], bf[nj][0], bf[nj][1]);
                    mma_f16(acc[mi][nj * 2 + 1], af[mi], bf[nj][2], bf[nj][3]);
                }
            }
        }
    }

    const int mRow = mBase + wm * 64 + (lane >> 2);
    const int nCol = nBase + wn * 32 + ((lane & 3) << 1);
    #pragma unroll
    for (int mi = 0; mi < 4; ++mi) {
        const int m0 = mRow + mi * 16;
        #pragma unroll
        for (int njh = 0; njh < 4; ++njh) {
            const int n = nCol + njh * 8;
            float2 b2 = *reinterpret_cast<const float2*>(&bias[n]);
            float2 o0 = make_float2(acc[mi][njh][0] + b2.x, acc[mi][njh][1] + b2.y);
            float2 o1 = make_float2(acc[mi][njh][2] + b2.x, acc[mi][njh][3] + b2.y);
            *reinterpret_cast<float2*>(&out[(size_t)m0 * OUT_DIM + n])       = o0;
            *reinterpret_cast<float2*>(&out[(size_t)(m0 + 8) * OUT_DIM + n]) = o1;
        }
    }
}

// ---------------------------------------------------------------------------
// Launch — cvt_half forked onto a side stream (overlaps pack+delta+quant),
// joined before the main GEMM that consumes g_xh.
// ---------------------------------------------------------------------------
extern "C" void kernel_launch(void* const* d_in, const int* in_sizes, int n_in,
                              void* d_out, int out_size) {
    const float *x = nullptr, *weight = nullptr, *Bd = nullptr,
                *Bu = nullptr, *bias = nullptr;
    for (int i = 0; i < n_in; i++) {
        switch (in_sizes[i]) {
            case 33554432: x      = (const float*)d_in[i]; break;  // 8192*4096
            case 45088768: weight = (const float*)d_in[i]; break;  // 11008*4096
            case 2113536:  Bd     = (const float*)d_in[i]; break;  // 11008*192
            case 786432:   Bu     = (const float*)d_in[i]; break;  // 192*4096
            case 11008:    bias   = (const float*)d_in[i]; break;
        }
    }
    if (!x && n_in > 0)      x      = (const float*)d_in[0];
    if (!weight && n_in > 1) weight = (const float*)d_in[1];
    if (!Bd && n_in > 2)     Bd     = (const float*)d_in[2];
    if (!Bu && n_in > 3)     Bu     = (const float*)d_in[3];
    if (!bias && n_in > 4)   bias   = (const float*)d_in[4];

    float *gw;
    __half *gxh, *gwh, *gbdp, *gbup;
    cudaGetSymbolAddress((void**)&gw,   g_w);
    cudaGetSymbolAddress((void**)&gxh,  g_xh);
    cudaGetSymbolAddress((void**)&gwh,  g_wh);
    cudaGetSymbolAddress((void**)&gbdp, g_bdp);
    cudaGetSymbolAddress((void**)&gbup, g_bup);

    cudaFuncSetAttribute(gemm_delta_f16,
                         cudaFuncAttributeMaxDynamicSharedMemorySize, GEMM_SMEM);
    cudaFuncSetAttribute(gemm_main_fp16,
                         cudaFuncAttributeMaxDynamicSharedMemorySize, GEMM_SMEM);

    // One-time host resources (no device memory involved).
    static cudaStream_t s_side = nullptr;
    static cudaEvent_t ev_fork = nullptr, ev_join = nullptr;
    if (s_side == nullptr) {
        cudaStreamCreateWithFlags(&s_side, cudaStreamNonBlocking);
        cudaEventCreateWithFlags(&ev_fork, cudaEventDisableTiming);
        cudaEventCreateWithFlags(&ev_join, cudaEventDisableTiming);
    }

    // Fork: x -> fp16 on side stream (independent of the delta chain).
    cudaEventRecord(ev_fork, 0);
    cudaStreamWaitEvent(s_side, ev_fork, 0);
    cvt_half_kernel<<<(33554432 / 4 + 255) / 256, 256, 0, s_side>>>(
        x, gxh, 33554432 / 4);
    cudaEventRecord(ev_join, s_side);

    // Main-stream chain: pack -> delta -> quant.
    pack_bd_kernel<<<((size_t)OUT_DIM * KPACK + 255) / 256, 256>>>(Bd, gbdp);
    pack_bu_kernel<<<dim3(RANK_ / 32, IN_DIM / 32), dim3(32, 8)>>>(Bu, gbup);
    gemm_delta_f16<<<dim3(IN_DIM / BN, OUT_DIM / BM), 256, GEMM_SMEM>>>(
        gbdp, gbup, weight, gw);
    quant_kernel<<<OUT_DIM, 256>>>(gw, gwh);

    // Join: main GEMM needs g_xh.
    cudaStreamWaitEvent(0, ev_join, 0);
    gemm_main_fp16<<<MTILES * NTILES, 256, GEMM_SMEM>>>(gxh, gwh, bias,
                                                        (float*)d_out);
}

// round 14
// speedup vs baseline: 1.0434x; 1.0016x over previous
#include <cuda_runtime.h>
#include <cuda_fp16.h>
#include <cstdint>
#include <cstddef>

// Problem dims (fixed by the dataset)
#define M_DIM   8192      // 4*2048 rows of x
#define IN_DIM  4096      // K of main GEMM
#define OUT_DIM 11008     // N of main GEMM
#define RANK_   192
#define KPACK   576       // 3 * RANK_  (compensated-product K concat)

// ---------------------------------------------------------------------------
// Scratch (static __device__ arrays — allocation-free per harness rules)
// ---------------------------------------------------------------------------
__device__ __align__(256) float  g_w  [(size_t)OUT_DIM * IN_DIM];  // weight+delta fp32
__device__ __align__(256) __half g_xh [(size_t)M_DIM  * IN_DIM];   // x as fp16
__device__ __align__(256) __half g_wh [(size_t)OUT_DIM * IN_DIM];  // quantized w fp16
__device__ __align__(256) __half g_bdp[(size_t)OUT_DIM * KPACK];   // [Ah|Ah|Al] of 64*Bd
__device__ __align__(256) __half g_bup[(size_t)IN_DIM * KPACK];    // [Bh|Bl|Bh] of 64*Bu, [N,K]

// ---------------------------------------------------------------------------
// x -> fp16
// ---------------------------------------------------------------------------
__global__ void cvt_half_kernel(const float* __restrict__ in,
                                __half* __restrict__ out, int n4) {
    int i = blockIdx.x * 256 + threadIdx.x;
    if (i < n4) {
        float4 v = reinterpret_cast<const float4*>(in)[i];
        __half2 h0 = __floats2half2_rn(v.x, v.y);
        __half2 h1 = __floats2half2_rn(v.z, v.w);
        uint2 p;
        p.x = *reinterpret_cast<uint32_t*>(&h0);
        p.y = *reinterpret_cast<uint32_t*>(&h1);
        reinterpret_cast<uint2*>(out)[i] = p;
    }
}

// ---------------------------------------------------------------------------
// Pack kernels: hi/lo fp16 split of 64*Bd / 64*Bu, K-concatenated so that a
// single fp16 GEMM computes Ah*Bh + Ah*Bl + Al*Bh (fp32-accurate product).
// ---------------------------------------------------------------------------
__global__ void pack_bd_kernel(const float* __restrict__ bd,
                               __half* __restrict__ out) {
    size_t i = (size_t)blockIdx.x * 256 + threadIdx.x;
    if (i < (size_t)OUT_DIM * KPACK) {
        int o = (int)(i / KPACK), c = (int)(i % KPACK);
        int r = (c < 192) ? c : ((c < 384) ? c - 192 : c - 384);
        float v = bd[(size_t)o * RANK_ + r] * 64.0f;
        __half h = __float2half_rn(v);
        out[i] = (c < 384) ? h : __float2half_rn(v - __half2float(h));
    }
}

// Tiled-transpose pack for Bu — coalesced reads AND writes.
__global__ void pack_bu_kernel(const float* __restrict__ bu,
                               __half* __restrict__ out) {
    __shared__ float t[32][33];
    const int r0 = blockIdx.x * 32;       // 6 blocks over rank
    const int n0 = blockIdx.y * 32;       // 128 blocks over IN_DIM
    const int tx = threadIdx.x, ty = threadIdx.y;   // 32 x 8

    #pragma unroll
    for (int j = 0; j < 32; j += 8)
        t[ty + j][tx] = bu[(size_t)(r0 + ty + j) * IN_DIM + n0 + tx];
    __syncthreads();

    #pragma unroll
    for (int j = 0; j < 32; j += 8) {
        const int n = n0 + ty + j;
        float v = t[tx][ty + j] * 64.0f;
        __half h = __float2half_rn(v);
        __half l = __float2half_rn(v - __half2float(h));
        __half* o = out + (size_t)n * KPACK + r0 + tx;
        o[0]   = h;
        o[192] = l;
        o[384] = h;
    }
}

// ---------------------------------------------------------------------------
// Row-wise 4-bit asymmetric fake quant: fp32 g_w (row cached) -> fp16 g_wh.
// ---------------------------------------------------------------------------
__global__ void quant_kernel(const float* __restrict__ w, __half* __restrict__ wh) {
    __shared__ float row[IN_DIM];
    __shared__ float smn[8], smx[8];
    __shared__ float s_scale, s_zero;

    const int rix = blockIdx.x;
    const float* p = w + (size_t)rix * IN_DIM;
    __half* po = wh + (size_t)rix * IN_DIM;
    const int tid = threadIdx.x;

    float mn = 0.0f, mx = 0.0f;
    #pragma unroll
    for (int i = tid; i < IN_DIM / 4; i += 256) {
        float4 v = reinterpret_cast<const float4*>(p)[i];
        reinterpret_cast<float4*>(row)[i] = v;
        mn = fminf(mn, fminf(fminf(v.x, v.y), fminf(v.z, v.w)));
        mx = fmaxf(mx, fmaxf(fmaxf(v.x, v.y), fmaxf(v.z, v.w)));
    }
    #pragma unroll
    for (int o = 16; o; o >>= 1) {
        mn = fminf(mn, __shfl_xor_sync(0xffffffffu, mn, o));
        mx = fmaxf(mx, __shfl_xor_sync(0xffffffffu, mx, o));
    }
    const int warp = tid >> 5, lane = tid & 31;
    if (lane == 0) { smn[warp] = mn; smx[warp] = mx; }
    __syncthreads();
    if (tid == 0) {
        float a = smn[0], b = smx[0];
        #pragma unroll
        for (int i = 1; i < 8; i++) { a = fminf(a, smn[i]); b = fmaxf(b, smx[i]); }
        float sc = fmaxf((b - a) / 15.0f, 1e-8f);
        s_scale = sc;
        s_zero  = rintf(-a / sc);
    }
    __syncthreads();
    const float sc = s_scale, z = s_zero;

    #pragma unroll
    for (int i = tid; i < IN_DIM / 4; i += 256) {
        float4 v = reinterpret_cast<float4*>(row)[i];
        float q0 = (fminf(fmaxf(rintf(v.x / sc) + z, 0.0f), 15.0f) - z) * sc;
        float q1 = (fminf(fmaxf(rintf(v.y / sc) + z, 0.0f), 15.0f) - z) * sc;
        float q2 = (fminf(fmaxf(rintf(v.z / sc) + z, 0.0f), 15.0f) - z) * sc;
        float q3 = (fminf(fmaxf(rintf(v.w / sc) + z, 0.0f), 15.0f) - z) * sc;
        __half2 h0 = __floats2half2_rn(q0, q1);
        __half2 h1 = __floats2half2_rn(q2, q3);
        uint2 pk;
        pk.x = *reinterpret_cast<uint32_t*>(&h0);
        pk.y = *reinterpret_cast<uint32_t*>(&h1);
        reinterpret_cast<uint2*>(po)[i] = pk;
    }
}

// ---------------------------------------------------------------------------
// Shared GEMM building blocks
// ---------------------------------------------------------------------------
__device__ __forceinline__ void cp16(uint32_t s, const void* g) {
    asm volatile("cp.async.cg.shared.global [%0], [%1], 16;\n" :: "r"(s), "l"(g));
}
__device__ __forceinline__ void ldsm_x4(uint32_t* r, uint32_t addr) {
    asm volatile("ldmatrix.sync.aligned.m8n8.x4.shared.b16 {%0,%1,%2,%3}, [%4];"
                 : "=r"(r[0]), "=r"(r[1]), "=r"(r[2]), "=r"(r[3]) : "r"(addr));
}
__device__ __forceinline__ void mma_f16(float* d, const uint32_t* a,
                                        uint32_t b0, uint32_t b1) {
    asm volatile(
        "mma.sync.aligned.m16n8k16.row.col.f32.f16.f16.f32 "
        "{%0,%1,%2,%3}, {%4,%5,%6,%7}, {%8,%9}, {%0,%1,%2,%3};\n"
        : "+f"(d[0]), "+f"(d[1]), "+f"(d[2]), "+f"(d[3])
        : "r"(a[0]), "r"(a[1]), "r"(a[2]), "r"(a[3]), "r"(b0), "r"(b1));
}

// Main GEMM geometry (R9/R11 optimum): CTA 128x128, 256 thr, 2 CTA/SM,
// K-chunk 64 halves, ROWB=144, 3-stage cp.async.
#define BM 128
#define BN 128
#define BKH 64
#define ROWB 144
#define A_BYTES (BM * ROWB)               // 18432
#define B_BYTES (BN * ROWB)               // 18432
#define STAGE_BYTES (A_BYTES + B_BYTES)   // 36864
#define NSTAGE 3
#define GEMM_SMEM (NSTAGE * STAGE_BYTES)  // 110592
#define KTILES_MAIN (IN_DIM / BKH)        // 64
#define MTILES (M_DIM / BM)               // 64
#define NTILES (OUT_DIM / BN)             // 86
#define EPI_STRIDE 136                    // floats; conflict-free staging

// Delta GEMM geometry: same 128x128 CTA / 256 thr / 2 CTA/SM, but BKH=32
// (5-stage, KTILES=18) to cut pipeline fill/drain fraction on short K.
#define DBKH 32
#define DROWB 80                          // 64B data + 16B pad
#define DA_BYTES (BM * DROWB)             // 10240
#define DB_BYTES (BN * DROWB)             // 10240
#define DSTAGE_BYTES (DA_BYTES + DB_BYTES)  // 20480
#define DNSTAGE 5
#define DGEMM_SMEM (DNSTAGE * DSTAGE_BYTES) // 102400
#define KTILES_DELTA (KPACK / DBKH)       // 18

// ---------------------------------------------------------------------------
// Delta GEMM (fp16, K=576): g_w[11008, 4096] = weight + (bdp @ bup^T)/4096
// ---------------------------------------------------------------------------
__global__ __launch_bounds__(256, 2)
void gemm_delta_f16(const __half* __restrict__ ap, const __half* __restrict__ bp,
                    const float* __restrict__ wgt, float* __restrict__ outw) {
    extern __shared__ __align__(128) unsigned char smem[];
    const uint32_t sb = (uint32_t)__cvta_generic_to_shared(smem);
    const int tid = threadIdx.x, warp = tid >> 5, lane = tid & 31;
    const int wm = warp & 1, wn = warp >> 1;   // 2M x 4N, warp tile 64x32

    const int mBase = blockIdx.y * BM, nBase = blockIdx.x * BN;

    // cp.async: A = 128 rows x 4 chunks(16B) = 512 → 2/thread; B same.
    const __half* gA[2]; uint32_t sAoff[2];
    const __half* gB[2]; uint32_t sBoff[2];
    #pragma unroll
    for (int i = 0; i < 2; i++) {
        int c = tid + i * 256;
        int r = c >> 2, s = c & 3;
        gA[i] = ap + (size_t)(mBase + r) * KPACK + s * 8;
        sAoff[i] = r * DROWB + s * 16;
        gB[i] = bp + (size_t)(nBase + r) * KPACK + s * 8;
        sBoff[i] = DA_BYTES + r * DROWB + s * 16;
    }

    auto issue = [&](int kt) {
        const uint32_t base = sb + (uint32_t)(kt % DNSTAGE) * DSTAGE_BYTES;
        const int koff = kt * DBKH;
        #pragma unroll
        for (int i = 0; i < 2; i++) cp16(base + sAoff[i], gA[i] + koff);
        #pragma unroll
        for (int i = 0; i < 2; i++) cp16(base + sBoff[i], gB[i] + koff);
        asm volatile("cp.async.commit_group;\n");
    };

    const int mat = lane >> 3, mrow = lane & 7;
    const uint32_t aAddr0 = (uint32_t)(wm * 64 + ((mat & 1) << 3) + mrow) * DROWB
                          + ((mat >> 1) << 4);
    const uint32_t bAddr0 = DA_BYTES
                          + (uint32_t)(wn * 32 + ((mat >> 1) << 3) + mrow) * DROWB
                          + ((mat & 1) << 4);

    float acc[4][4][4];
    #pragma unroll
    for (int i = 0; i < 4; i++)
        #pragma unroll
        for (int j = 0; j < 4; j++)
            #pragma unroll
            for (int k = 0; k < 4; k++) acc[i][j][k] = 0.0f;

    issue(0); issue(1); issue(2); issue(3);

    for (int kt = 0; kt < KTILES_DELTA; ++kt) {
        const int rem = KTILES_DELTA - 1 - kt;   // groups still to land after kt
        if (rem >= 3)      { asm volatile("cp.async.wait_group 3;\n"); }
        else if (rem == 2) { asm volatile("cp.async.wait_group 2;\n"); }
        else if (rem == 1) { asm volatile("cp.async.wait_group 1;\n"); }
        else               { asm volatile("cp.async.wait_group 0;\n"); }
        __syncthreads();
        if (kt + 4 < KTILES_DELTA) issue(kt + 4);

        const uint32_t base = sb + (uint32_t)(kt % DNSTAGE) * DSTAGE_BYTES;

        #pragma unroll
        for (int kk = 0; kk < 2; ++kk) {         // 2 x k16 within 32-half tile
            uint32_t af[4][4], bf[2][4];
            #pragma unroll
            for (int mi = 0; mi < 4; ++mi)
                ldsm_x4(af[mi], base + aAddr0 + mi * (16 * DROWB) + kk * 32);
            #pragma unroll
            for (int nj = 0; nj < 2; ++nj)
                ldsm_x4(bf[nj], base + bAddr0 + nj * (16 * DROWB) + kk * 32);
            #pragma unroll
            for (int mi = 0; mi < 4; ++mi) {
                #pragma unroll
                for (int nj = 0; nj < 2; ++nj) {
                    mma_f16(acc[mi][nj * 2],     af[mi], bf[nj][0], bf[nj][1]);
                    mma_f16(acc[mi][nj * 2 + 1], af[mi], bf[nj][2], bf[nj][3]);
                }
            }
        }
    }

    // Epilogue via smem staging (conflict-free), then coalesced float4 stream.
    __syncthreads();
    float* st = reinterpret_cast<float*>(smem);
    {
        const int mr = wm * 64 + (lane >> 2);
        const int nc = wn * 32 + ((lane & 3) << 1);
        #pragma unroll
        for (int mi = 0; mi < 4; ++mi) {
            const int m0 = mr + mi * 16;
            #pragma unroll
            for (int njh = 0; njh < 4; ++njh) {
                const int n = nc + njh * 8;
                st[m0 * EPI_STRIDE + n]           = acc[mi][njh][0];
                st[m0 * EPI_STRIDE + n + 1]       = acc[mi][njh][1];
                st[(m0 + 8) * EPI_STRIDE + n]     = acc[mi][njh][2];
                st[(m0 + 8) * EPI_STRIDE + n + 1] = acc[mi][njh][3];
            }
        }
    }
    __syncthreads();
    const float SC = 1.0f / 4096.0f;
    #pragma unroll
    for (int it = 0; it < 16; ++it) {
        int i = tid + it * 256;                  // 0..4095 float4 slots
        int row = i >> 5, c4 = i & 31;
        float4 v = *reinterpret_cast<float4*>(&st[row * EPI_STRIDE + c4 * 4]);
        size_t gofs = (size_t)(mBase + row) * IN_DIM + nBase + c4 * 4;
        float4 w4 = *reinterpret_cast<const float4*>(&wgt[gofs]);
        v.x = v.x * SC + w4.x;
        v.y = v.y * SC + w4.y;
        v.z = v.z * SC + w4.z;
        v.w = v.w * SC + w4.w;
        *reinterpret_cast<float4*>(&outw[gofs]) = v;
    }
}

// ---------------------------------------------------------------------------
// Main GEMM: out[8192,11008] = xh @ wh^T + bias  (R9/R11 config, unchanged)
// ---------------------------------------------------------------------------
__global__ __launch_bounds__(256, 2)
void gemm_main_fp16(const __half* __restrict__ xh, const __half* __restrict__ wh,
                    const float* __restrict__ bias, float* __restrict__ out) {
    extern __shared__ __align__(128) unsigned char smem[];
    const uint32_t sb = (uint32_t)__cvta_generic_to_shared(smem);
    const int tid = threadIdx.x, warp = tid >> 5, lane = tid & 31;
    const int wm = warp & 1, wn = warp >> 1;   // 2M x 4N warps, warp tile 64x32

    // Grid swizzle: 8-wide n-supercolumns (86 = 10*8 + 6).
    int g = blockIdx.x, mTile, nTile;
    if (g < MTILES * 80) { int sc = g >> 9, loc = g & 511; nTile = sc * 8 + (loc & 7); mTile = loc >> 3; }
    else                 { int loc = g - MTILES * 80; nTile = 80 + loc % 6; mTile = loc / 6; }
    const int mBase = mTile * BM, nBase = nTile * BN;

    const __half* gA[4]; uint32_t sAoff[4];
    const __half* gB[4]; uint32_t sBoff[4];
    #pragma unroll
    for (int i = 0; i < 4; i++) {
        int c = tid + i * 256;
        int r = c >> 3, s = c & 7;
        gA[i] = xh + (size_t)(mBase + r) * IN_DIM + s * 8;
        sAoff[i] = r * ROWB + s * 16;
        gB[i] = wh + (size_t)(nBase + r) * IN_DIM + s * 8;
        sBoff[i] = A_BYTES + r * ROWB + s * 16;
    }

    auto issue = [&](int kt) {
        const uint32_t base = sb + (uint32_t)(kt % NSTAGE) * STAGE_BYTES;
        const int koff = kt * BKH;
        #pragma unroll
        for (int i = 0; i < 4; i++) cp16(base + sAoff[i], gA[i] + koff);
        #pragma unroll
        for (int i = 0; i < 4; i++) cp16(base + sBoff[i], gB[i] + koff);
        asm volatile("cp.async.commit_group;\n");
    };

    const int mat = lane >> 3, mrow = lane & 7;
    const uint32_t aAddr0 = (uint32_t)(wm * 64 + ((mat & 1) << 3) + mrow) * ROWB
                          + ((mat >> 1) << 4);
    const uint32_t bAddr0 = A_BYTES
                          + (uint32_t)(wn * 32 + ((mat >> 1) << 3) + mrow) * ROWB
                          + ((mat & 1) << 4);

    float acc[4][4][4];
    #pragma unroll
    for (int i = 0; i < 4; i++)
        #pragma unroll
        for (int j = 0; j < 4; j++)
            #pragma unroll
            for (int k = 0; k < 4; k++) acc[i][j][k] = 0.0f;

    issue(0); issue(1);

    for (int kt = 0; kt < KTILES_MAIN; ++kt) {
        if (kt < KTILES_MAIN - 1) { asm volatile("cp.async.wait_group 1;\n"); }
        else                      { asm volatile("cp.async.wait_group 0;\n"); }
        __syncthreads();
        if (kt + 2 < KTILES_MAIN) issue(kt + 2);

        const uint32_t base = sb + (uint32_t)(kt % NSTAGE) * STAGE_BYTES;

        #pragma unroll
        for (int kk = 0; kk < 4; ++kk) {
            uint32_t af[4][4], bf[2][4];
            #pragma unroll
            for (int mi = 0; mi < 4; ++mi)
                ldsm_x4(af[mi], base + aAddr0 + mi * (16 * ROWB) + kk * 32);
            #pragma unroll
            for (int nj = 0; nj < 2; ++nj)
                ldsm_x4(bf[nj], base + bAddr0 + nj * (16 * ROWB) + kk * 32);
            #pragma unroll
            for (int mi = 0; mi < 4; ++mi) {
                #pragma unroll
                for (int nj = 0; nj < 2; ++nj) {
                    mma_f16(acc[mi][nj * 2],     af[mi], bf[nj][0], bf[nj][1]);
                    mma_f16(acc[mi][nj * 2 + 1], af[mi], bf[nj][2], bf[nj][3]);
                }
            }
        }
    }

    const int mRow = mBase + wm * 64 + (lane >> 2);
    const int nCol = nBase + wn * 32 + ((lane & 3) << 1);
    #pragma unroll
    for (int mi = 0; mi < 4; ++mi) {
        const int m0 = mRow + mi * 16;
        #pragma unroll
        for (int njh = 0; njh < 4; ++njh) {
            const int n = nCol + njh * 8;
            float2 b2 = *reinterpret_cast<const float2*>(&bias[n]);
            float2 o0 = make_float2(acc[mi][njh][0] + b2.x, acc[mi][njh][1] + b2.y);
            float2 o1 = make_float2(acc[mi][njh][2] + b2.x, acc[mi][njh][3] + b2.y);
            *reinterpret_cast<float2*>(&out[(size_t)m0 * OUT_DIM + n])       = o0;
            *reinterpret_cast<float2*>(&out[(size_t)(m0 + 8) * OUT_DIM + n]) = o1;
        }
    }
}

// ---------------------------------------------------------------------------
// Launch — pack_bd + cvt_half forked onto a side stream:
//   side: pack_bd -> ev_pack -> cvt_half -> ev_join
//   main: pack_bu -> wait(ev_pack) -> delta -> quant -> wait(ev_join) -> main
// ---------------------------------------------------------------------------
extern "C" void kernel_launch(void* const* d_in, const int* in_sizes, int n_in,
                              void* d_out, int out_size) {
    const float *x = nullptr, *weight = nullptr, *Bd = nullptr,
                *Bu = nullptr, *bias = nullptr;
    for (int i = 0; i < n_in; i++) {
        switch (in_sizes[i]) {
            case 33554432: x      = (const float*)d_in[i]; break;  // 8192*4096
            case 45088768: weight = (const float*)d_in[i]; break;  // 11008*4096
            case 2113536:  Bd     = (const float*)d_in[i]; break;  // 11008*192
            case 786432:   Bu     = (const float*)d_in[i]; break;  // 192*4096
            case 11008:    bias   = (const float*)d_in[i]; break;
        }
    }
    if (!x && n_in > 0)      x      = (const float*)d_in[0];
    if (!weight && n_in > 1) weight = (const float*)d_in[1];
    if (!Bd && n_in > 2)     Bd     = (const float*)d_in[2];
    if (!Bu && n_in > 3)     Bu     = (const float*)d_in[3];
    if (!bias && n_in > 4)   bias   = (const float*)d_in[4];

    float *gw;
    __half *gxh, *gwh, *gbdp, *gbup;
    cudaGetSymbolAddress((void**)&gw,   g_w);
    cudaGetSymbolAddress((void**)&gxh,  g_xh);
    cudaGetSymbolAddress((void**)&gwh,  g_wh);
    cudaGetSymbolAddress((void**)&gbdp, g_bdp);
    cudaGetSymbolAddress((void**)&gbup, g_bup);

    cudaFuncSetAttribute(gemm_delta_f16,
                         cudaFuncAttributeMaxDynamicSharedMemorySize, DGEMM_SMEM);
    cudaFuncSetAttribute(gemm_main_fp16,
                         cudaFuncAttributeMaxDynamicSharedMemorySize, GEMM_SMEM);

    // One-time host resources (no device memory involved).
    static cudaStream_t s_side = nullptr;
    static cudaEvent_t ev_fork = nullptr, ev_pack = nullptr, ev_join = nullptr;
    if (s_side == nullptr) {
        cudaStreamCreateWithFlags(&s_side, cudaStreamNonBlocking);
        cudaEventCreateWithFlags(&ev_fork, cudaEventDisableTiming);
        cudaEventCreateWithFlags(&ev_pack, cudaEventDisableTiming);
        cudaEventCreateWithFlags(&ev_join, cudaEventDisableTiming);
    }

    // Fork side stream: pack_bd (feeds delta), then cvt_half (feeds main GEMM).
    cudaEventRecord(ev_fork, 0);
    cudaStreamWaitEvent(s_side, ev_fork, 0);
    pack_bd_kernel<<<((size_t)OUT_DIM * KPACK + 255) / 256, 256, 0, s_side>>>(
        Bd, gbdp);
    cudaEventRecord(ev_pack, s_side);
    cvt_half_kernel<<<(33554432 / 4 + 255) / 256, 256, 0, s_side>>>(
        x, gxh, 33554432 / 4);
    cudaEventRecord(ev_join, s_side);

    // Main-stream chain: pack_bu || pack_bd, then delta -> quant.
    pack_bu_kernel<<<dim3(RANK_ / 32, IN_DIM / 32), dim3(32, 8)>>>(Bu, gbup);
    cudaStreamWaitEvent(0, ev_pack, 0);
    gemm_delta_f16<<<dim3(IN_DIM / BN, OUT_DIM / BM), 256, DGEMM_SMEM>>>(
        gbdp, gbup, weight, gw);
    quant_kernel<<<OUT_DIM, 256>>>(gw, gwh);

    // Join: main GEMM needs g_xh.
    cudaStreamWaitEvent(0, ev_join, 0);
    gemm_main_fp16<<<MTILES * NTILES, 256, GEMM_SMEM>>>(gxh, gwh, bias,
                                                        (float*)d_out);
}